// round 11
// baseline (speedup 1.0000x reference)
#include <cuda_runtime.h>
#include <cuda_fp16.h>
#include <mma.h>
#include <cstdint>

using namespace nvcuda;

#define T_  512
#define B_  64
#define H_  1024
#define G_  4096
#define BH  (B_*H_)
#define TBH ((size_t)T_*B_*H_)
#define NCTA 128

// ---------------- device scratch (no allocations allowed) ----------------
__device__ float    g_xin[(size_t)T_*B_*G_];     // input projection (fp32, per layer)
__device__ __half   g_xh[TBH];                   // x rounded to fp16
__device__ __half   g_wh[(size_t)2*G_*H_];       // w_ih rounded to fp16
__device__ __half   g_s0h[TBH];                  // layer-0 seq (fp16, feeds layer-1 gemm)
__device__ __half   g_h[2*BH];                   // double-buffered h state (fp16)
__device__ unsigned g_flag[NCTA];                // per-CTA step flags

__device__ __forceinline__ uint32_t smem_u32(const void* p) {
    uint32_t a;
    asm("{ .reg .u64 t; cvta.to.shared.u64 t, %1; cvt.u32.u64 %0, t; }" : "=r"(a) : "l"(p));
    return a;
}
__device__ __forceinline__ unsigned ld_acq(const unsigned* p) {
    unsigned v;
    asm volatile("ld.acquire.gpu.global.u32 %0, [%1];" : "=r"(v) : "l"(p) : "memory");
    return v;
}
__device__ __forceinline__ void st_rel(unsigned* p, unsigned v) {
    asm volatile("st.release.gpu.global.u32 [%0], %1;" :: "l"(p), "r"(v) : "memory");
}
#define CP_ASYNC16(dst_u32, src_ptr) \
    asm volatile("cp.async.cg.shared.global [%0], [%1], 16;" :: "r"(dst_u32), "l"(src_ptr))
#define CP_COMMIT() asm volatile("cp.async.commit_group;" ::: "memory")
#define CP_WAIT(n)  asm volatile("cp.async.wait_group %0;" :: "n"(n) : "memory")

// ---------------- init: zero h buffers + flags ----------------
__global__ void init_kernel() {
    int i = blockIdx.x * blockDim.x + threadIdx.x;   // 32768 threads
    float* hz = reinterpret_cast<float*>(g_h);
    hz[i] = 0.0f; hz[i + 32768] = 0.0f;
    if (i < NCTA) g_flag[i] = 0u;
}

// ---------------- pre-round x and w_ih to fp16 ----------------
#define XF4 (TBH/4)
#define WF4 ((size_t)2*G_*H_/4)
__global__ void round_all(const float* __restrict__ x, const float* __restrict__ wih) {
    const size_t stride = (size_t)gridDim.x * blockDim.x;
    for (size_t i = (size_t)blockIdx.x * blockDim.x + threadIdx.x; i < XF4 + WF4; i += stride) {
        float4 v; __half2* dst;
        if (i < XF4) {
            v = reinterpret_cast<const float4*>(x)[i];
            dst = reinterpret_cast<__half2*>(g_xh) + i * 2;
        } else {
            v = reinterpret_cast<const float4*>(wih)[i - XF4];
            dst = reinterpret_cast<__half2*>(g_wh) + (i - XF4) * 2;
        }
        dst[0] = __floats2half2_rn(v.x, v.y);
        dst[1] = __floats2half2_rn(v.z, v.w);
    }
}

// ============ Stage 1: xin[32768,4096] = A[32768,1024] @ W[4096,1024]^T (fp16) ============
#define GA 9216
#define GX_SMEM (4*GA*2)
__global__ __launch_bounds__(256) void gemm_xin(int layer) {
    extern __shared__ __half smh[];
    __half* As = smh;
    __half* Bs = smh + 2*GA;

    const __half* A = (layer == 0) ? g_xh : g_s0h;
    const __half* W = g_wh + (size_t)layer * (size_t)G_ * H_;

    const int tid  = threadIdx.x;
    const int warp = tid >> 5;
    const int wm   = warp >> 2;
    const int wn   = warp & 3;
    const size_t m0 = (size_t)blockIdx.y * 128;
    const int    n0 = blockIdx.x * 128;

    const int r8 = tid >> 3, c8 = (tid & 7) << 3;
    const uint32_t sa = smem_u32(As), sb = smem_u32(Bs);

    wmma::fragment<wmma::accumulator,16,16,16,float> acc[4][2];
    #pragma unroll
    for (int mi = 0; mi < 4; mi++)
        #pragma unroll
        for (int ni = 0; ni < 2; ni++)
            wmma::fill_fragment(acc[mi][ni], 0.0f);

    #pragma unroll
    for (int i = 0; i < 4; i++) {
        int rr = r8 + i*32;
        CP_ASYNC16(sa + (uint32_t)(rr*72 + c8)*2, &A[(m0 + rr)*1024 + c8]);
        CP_ASYNC16(sb + (uint32_t)(rr*72 + c8)*2, &W[(size_t)(n0 + rr)*1024 + c8]);
    }
    CP_COMMIT();

    for (int it = 0; it < 16; ++it) {
        const int buf = it & 1;
        if (it < 15) {
            const int kc = (it + 1) * 64;
            const uint32_t da = sa + (uint32_t)((buf^1)*GA)*2;
            const uint32_t db = sb + (uint32_t)((buf^1)*GA)*2;
            #pragma unroll
            for (int i = 0; i < 4; i++) {
                int rr = r8 + i*32;
                CP_ASYNC16(da + (uint32_t)(rr*72 + c8)*2, &A[(m0 + rr)*1024 + kc + c8]);
                CP_ASYNC16(db + (uint32_t)(rr*72 + c8)*2, &W[(size_t)(n0 + rr)*1024 + kc + c8]);
            }
            CP_COMMIT();
            CP_WAIT(1);
        } else {
            CP_WAIT(0);
        }
        __syncthreads();
        const __half* Ab = As + buf*GA;
        const __half* Bb = Bs + buf*GA;
        #pragma unroll
        for (int k16 = 0; k16 < 4; k16++) {
            wmma::fragment<wmma::matrix_a,16,16,16,__half,wmma::row_major> af[4];
            wmma::fragment<wmma::matrix_b,16,16,16,__half,wmma::col_major> bf[2];
            #pragma unroll
            for (int mi = 0; mi < 4; mi++)
                wmma::load_matrix_sync(af[mi], &Ab[(wm*64 + mi*16)*72 + k16*16], 72);
            #pragma unroll
            for (int ni = 0; ni < 2; ni++)
                wmma::load_matrix_sync(bf[ni], &Bb[(wn*32 + ni*16)*72 + k16*16], 72);
            #pragma unroll
            for (int mi = 0; mi < 4; mi++)
                #pragma unroll
                for (int ni = 0; ni < 2; ni++)
                    wmma::mma_sync(acc[mi][ni], af[mi], bf[ni], acc[mi][ni]);
        }
        __syncthreads();
    }
    #pragma unroll
    for (int mi = 0; mi < 4; mi++)
        #pragma unroll
        for (int ni = 0; ni < 2; ni++)
            wmma::store_matrix_sync(
                &g_xin[(m0 + wm*64 + mi*16)*(size_t)G_ + n0 + wn*32 + ni*16],
                acc[mi][ni], G_, wmma::mem_row_major);
}

// ============ Stage 2: persistent recurrence (fp16), 512 threads, dataflow flags ============
// byte offsets: Ws half 32x1032 @0 (66048B) | Hs half 2x(64x264) @66048 (67584B)
//               Ps float 16x16x36 @133632 (36864B) | Cs 512 @170496 | Bsum 32 @172544
#define RB_WS   0
#define RB_HS   66048
#define RB_PS   133632
#define RB_CS   170496
#define RB_BS   172544
#define SMEM_BYTES 172672
#define HS_BUF  16896                      // halves per Hs buffer (64*264)

__global__ __launch_bounds__(512) void lstm_rec(const float* __restrict__ whh,
                                                const float* __restrict__ bih,
                                                const float* __restrict__ bhh,
                                                float* __restrict__ out,
                                                int layer) {
    extern __shared__ char smc[];
    __half* Ws   = reinterpret_cast<__half*>(smc + RB_WS);
    __half* Hs   = reinterpret_cast<__half*>(smc + RB_HS);
    float*  Ps   = reinterpret_cast<float*>(smc + RB_PS);
    float*  Cs   = reinterpret_cast<float*>(smc + RB_CS);
    float*  Bsum = reinterpret_cast<float*>(smc + RB_BS);

    const int tid  = threadIdx.x;
    const int warp = tid >> 5;
    const int mq   = warp & 3;            // M quarter (16 rows)
    const int kq   = warp >> 2;           // K quarter within each 256-chunk
    const int j0   = blockIdx.x * 8;

    const float* whh_l = whh + (size_t)layer * (size_t)G_ * H_;
    const float* bih_l = bih + (size_t)layer * G_;
    const float* bhh_l = bhh + (size_t)layer * G_;
    float* hn_out = out + TBH + (size_t)layer * BH;
    float* cn_out = out + TBH + 2*(size_t)BH + (size_t)layer * BH;
    const uint32_t hs_b = smem_u32(Hs);

    const int fidx = (tid & 31);                // flag lane within chunk group

    // Stage w_hh rows (n = gate*8 + jj) as fp16.  8192 float4 over 512 threads.
    #pragma unroll 4
    for (int i = 0; i < 16; i++) {
        int idx = i*512 + tid;
        int rr = idx >> 8;
        int cc = (idx & 255) << 2;
        int grow = (rr >> 3) * H_ + j0 + (rr & 7);
        float4 v = *reinterpret_cast<const float4*>(&whh_l[(size_t)grow * H_ + cc]);
        __half2* d = reinterpret_cast<__half2*>(&Ws[rr*1032 + cc]);
        d[0] = __floats2half2_rn(v.x, v.y);
        d[1] = __floats2half2_rn(v.z, v.w);
    }
    if (tid < 32) {
        int grow = (tid >> 3) * H_ + j0 + (tid & 7);
        Bsum[tid] = bih_l[grow] + bhh_l[grow];
    }
    if (tid < 512) Cs[tid] = 0.0f;
    __syncthreads();

    const int b0 = tid >> 3, jj = tid & 7;

    for (int t = 0; t < T_; ++t) {
        const __half* hprev = g_h + (size_t)(t & 1) * BH;
        __half*       hnext = g_h + (size_t)((t + 1) & 1) * BH;
        const unsigned tgt = (unsigned)t;

        // xin prefetch (independent of h): one batch-row per thread
        float xr[4];
        {
            const float* p0 = g_xin + ((size_t)t * B_ + b0) * G_ + j0 + jj;
            xr[0] = p0[0]; xr[1] = p0[1024]; xr[2] = p0[2048]; xr[3] = p0[3072];
        }

        wmma::fragment<wmma::accumulator,16,16,16,float> acc[2];
        wmma::fill_fragment(acc[0], 0.0f);
        wmma::fill_fragment(acc[1], 0.0f);

        // prologue: dataflow wait on chunk 0's producers, async-load chunk 0
        if (ld_acq(&g_flag[fidx]) < tgt)
            while (ld_acq(&g_flag[fidx]) < tgt) __nanosleep(20);
        #pragma unroll
        for (int i = 0; i < 4; i++) {
            int idx = i*512 + tid;                      // 2048 x 16B
            int rr = idx >> 5, cc8 = (idx & 31) << 3;
            CP_ASYNC16(hs_b + (uint32_t)(rr*264 + cc8)*2, &hprev[(size_t)rr*H_ + cc8]);
        }
        CP_COMMIT();

        for (int ch = 0; ch < 4; ch++) {
            const int buf = ch & 1;
            if (ch < 3) {
                const int kc = (ch + 1) * 256;
                const unsigned* fl = &g_flag[32*(ch+1) + fidx];
                if (ld_acq(fl) < tgt)
                    while (ld_acq(fl) < tgt) __nanosleep(20);
                const uint32_t dh = hs_b + (uint32_t)((buf^1)*HS_BUF)*2;
                #pragma unroll
                for (int i = 0; i < 4; i++) {
                    int idx = i*512 + tid;
                    int rr = idx >> 5, cc8 = (idx & 31) << 3;
                    CP_ASYNC16(dh + (uint32_t)(rr*264 + cc8)*2, &hprev[(size_t)rr*H_ + kc + cc8]);
                }
                CP_COMMIT();
                CP_WAIT(1);
            } else {
                CP_WAIT(0);
            }
            __syncthreads();
            const __half* Hb = Hs + buf*HS_BUF;
            #pragma unroll
            for (int k16 = 0; k16 < 4; k16++) {
                const int koff = kq*64 + k16*16;
                wmma::fragment<wmma::matrix_a,16,16,16,__half,wmma::row_major> af;
                wmma::fragment<wmma::matrix_b,16,16,16,__half,wmma::col_major> bf[2];
                wmma::load_matrix_sync(af, &Hb[(mq*16)*264 + koff], 264);
                wmma::load_matrix_sync(bf[0], &Ws[          ch*256 + koff], 1032);
                wmma::load_matrix_sync(bf[1], &Ws[16*1032 + ch*256 + koff], 1032);
                wmma::mma_sync(acc[0], af, bf[0], acc[0]);
                wmma::mma_sync(acc[1], af, bf[1], acc[1]);
            }
            __syncthreads();
        }

        // per-warp partials: 16x32 tile at Ps[warp*576], row stride 36
        wmma::store_matrix_sync(&Ps[warp*576     ], acc[0], 36, wmma::mem_row_major);
        wmma::store_matrix_sync(&Ps[warp*576 + 16], acc[1], 36, wmma::mem_row_major);
        __syncthreads();

        // fused K-reduction + gate epilogue: exactly one element per thread
        {
            const int b  = b0;
            const int mqe = b >> 4, br = b & 15;
            float s[4];
            #pragma unroll
            for (int g = 0; g < 4; g++) {
                int n = g*8 + jj;
                float a = Ps[(0*4+mqe)*576 + br*36 + n]
                        + Ps[(1*4+mqe)*576 + br*36 + n]
                        + Ps[(2*4+mqe)*576 + br*36 + n]
                        + Ps[(3*4+mqe)*576 + br*36 + n];
                s[g] = a + xr[g] + Bsum[n];
            }
            float si = 1.0f / (1.0f + __expf(-s[0]));
            float sf = 1.0f / (1.0f + __expf(-s[1]));
            float so = 1.0f / (1.0f + __expf(-s[3]));
            float cv = sf * Cs[tid] + si * tanhf(s[2]);
            float hv = so * tanhf(cv);
            Cs[tid] = cv;
            hnext[(size_t)b*H_ + j0 + jj] = __float2half_rn(hv);
            if (layer == 0)
                g_s0h[((size_t)t * B_ + b) * H_ + j0 + jj] = __float2half_rn(hv);
            else
                out[((size_t)t * B_ + b) * H_ + j0 + jj] = hv;
            if (t == T_ - 1) {
                hn_out[(size_t)b*H_ + j0 + jj] = hv;
                cn_out[(size_t)b*H_ + j0 + jj] = cv;
            }
        }
        // publish: fence, sync, one release-store
        __threadfence();
        __syncthreads();
        if (tid == 0) st_rel(&g_flag[blockIdx.x], (unsigned)(t + 1));
    }
}

// ---------------- launch ----------------
extern "C" void kernel_launch(void* const* d_in, const int* in_sizes, int n_in,
                              void* d_out, int out_size) {
    const float* x   = (const float*)d_in[0];
    const float* wih = (const float*)d_in[1];
    const float* whh = (const float*)d_in[2];
    const float* bih = (const float*)d_in[3];
    const float* bhh = (const float*)d_in[4];
    float* out = (float*)d_out;

    cudaFuncSetAttribute(lstm_rec, cudaFuncAttributeMaxDynamicSharedMemorySize, SMEM_BYTES);
    cudaFuncSetAttribute(gemm_xin, cudaFuncAttributeMaxDynamicSharedMemorySize, GX_SMEM);

    init_kernel<<<128, 256>>>();                                  // #1
    round_all<<<4096, 256>>>(x, wih);                             // #2
    gemm_xin<<<dim3(32, 256), 256, GX_SMEM>>>(0);                 // #3
    lstm_rec<<<NCTA, 512, SMEM_BYTES>>>(whh, bih, bhh, out, 0);   // #4 -> ncu slot 6
    init_kernel<<<128, 256>>>();
    gemm_xin<<<dim3(32, 256), 256, GX_SMEM>>>(1);
    lstm_rec<<<NCTA, 512, SMEM_BYTES>>>(whh, bih, bhh, out, 1);
}

// round 12
// speedup vs baseline: 1.6665x; 1.6665x over previous
#include <cuda_runtime.h>
#include <cuda_fp16.h>
#include <mma.h>
#include <cstdint>

using namespace nvcuda;

#define T_  512
#define B_  64
#define H_  1024
#define G_  4096
#define BH  (B_*H_)
#define TBH ((size_t)T_*B_*H_)
#define NCTA 128

// ---------------- device scratch (no allocations allowed) ----------------
__device__ float    g_xin[(size_t)T_*B_*G_];     // input projection (fp32, per layer)
__device__ __half   g_xh[TBH];                   // x rounded to fp16
__device__ __half   g_wh[(size_t)2*G_*H_];       // w_ih rounded to fp16
__device__ __half   g_s0h[TBH];                  // layer-0 seq (fp16, feeds layer-1 gemm)
__device__ __half   g_h[2*BH];                   // double-buffered h state (fp16)
__device__ unsigned g_flag[NCTA];                // per-CTA step flags

__device__ __forceinline__ uint32_t smem_u32(const void* p) {
    uint32_t a;
    asm("{ .reg .u64 t; cvta.to.shared.u64 t, %1; cvt.u32.u64 %0, t; }" : "=r"(a) : "l"(p));
    return a;
}
__device__ __forceinline__ unsigned ld_acq(const unsigned* p) {
    unsigned v;
    asm volatile("ld.acquire.gpu.global.u32 %0, [%1];" : "=r"(v) : "l"(p) : "memory");
    return v;
}
__device__ __forceinline__ void st_rel(unsigned* p, unsigned v) {
    asm volatile("st.release.gpu.global.u32 [%0], %1;" :: "l"(p), "r"(v) : "memory");
}
#define CP_ASYNC16(dst_u32, src_ptr) \
    asm volatile("cp.async.cg.shared.global [%0], [%1], 16;" :: "r"(dst_u32), "l"(src_ptr))
#define CP_COMMIT() asm volatile("cp.async.commit_group;" ::: "memory")
#define CP_WAIT(n)  asm volatile("cp.async.wait_group %0;" :: "n"(n) : "memory")

// ---------------- init: zero h buffers + flags ----------------
__global__ void init_kernel() {
    int i = blockIdx.x * blockDim.x + threadIdx.x;   // 32768 threads
    float* hz = reinterpret_cast<float*>(g_h);
    hz[i] = 0.0f; hz[i + 32768] = 0.0f;
    if (i < NCTA) g_flag[i] = 0u;
}

// ---------------- pre-round x and w_ih to fp16 ----------------
#define XF4 (TBH/4)
#define WF4 ((size_t)2*G_*H_/4)
__global__ void round_all(const float* __restrict__ x, const float* __restrict__ wih) {
    const size_t stride = (size_t)gridDim.x * blockDim.x;
    for (size_t i = (size_t)blockIdx.x * blockDim.x + threadIdx.x; i < XF4 + WF4; i += stride) {
        float4 v; __half2* dst;
        if (i < XF4) {
            v = reinterpret_cast<const float4*>(x)[i];
            dst = reinterpret_cast<__half2*>(g_xh) + i * 2;
        } else {
            v = reinterpret_cast<const float4*>(wih)[i - XF4];
            dst = reinterpret_cast<__half2*>(g_wh) + (i - XF4) * 2;
        }
        dst[0] = __floats2half2_rn(v.x, v.y);
        dst[1] = __floats2half2_rn(v.z, v.w);
    }
}

// ============ Stage 1: xin[32768,4096] = A[32768,1024] @ W[4096,1024]^T (fp16) ============
#define GA 9216
#define GX_SMEM (4*GA*2)
__global__ __launch_bounds__(256) void gemm_xin(int layer) {
    extern __shared__ __half smh[];
    __half* As = smh;
    __half* Bs = smh + 2*GA;

    const __half* A = (layer == 0) ? g_xh : g_s0h;
    const __half* W = g_wh + (size_t)layer * (size_t)G_ * H_;

    const int tid  = threadIdx.x;
    const int warp = tid >> 5;
    const int wm   = warp >> 2;
    const int wn   = warp & 3;
    const size_t m0 = (size_t)blockIdx.y * 128;
    const int    n0 = blockIdx.x * 128;

    const int r8 = tid >> 3, c8 = (tid & 7) << 3;
    const uint32_t sa = smem_u32(As), sb = smem_u32(Bs);

    wmma::fragment<wmma::accumulator,16,16,16,float> acc[4][2];
    #pragma unroll
    for (int mi = 0; mi < 4; mi++)
        #pragma unroll
        for (int ni = 0; ni < 2; ni++)
            wmma::fill_fragment(acc[mi][ni], 0.0f);

    #pragma unroll
    for (int i = 0; i < 4; i++) {
        int rr = r8 + i*32;
        CP_ASYNC16(sa + (uint32_t)(rr*72 + c8)*2, &A[(m0 + rr)*1024 + c8]);
        CP_ASYNC16(sb + (uint32_t)(rr*72 + c8)*2, &W[(size_t)(n0 + rr)*1024 + c8]);
    }
    CP_COMMIT();

    for (int it = 0; it < 16; ++it) {
        const int buf = it & 1;
        if (it < 15) {
            const int kc = (it + 1) * 64;
            const uint32_t da = sa + (uint32_t)((buf^1)*GA)*2;
            const uint32_t db = sb + (uint32_t)((buf^1)*GA)*2;
            #pragma unroll
            for (int i = 0; i < 4; i++) {
                int rr = r8 + i*32;
                CP_ASYNC16(da + (uint32_t)(rr*72 + c8)*2, &A[(m0 + rr)*1024 + kc + c8]);
                CP_ASYNC16(db + (uint32_t)(rr*72 + c8)*2, &W[(size_t)(n0 + rr)*1024 + kc + c8]);
            }
            CP_COMMIT();
            CP_WAIT(1);
        } else {
            CP_WAIT(0);
        }
        __syncthreads();
        const __half* Ab = As + buf*GA;
        const __half* Bb = Bs + buf*GA;
        #pragma unroll
        for (int k16 = 0; k16 < 4; k16++) {
            wmma::fragment<wmma::matrix_a,16,16,16,__half,wmma::row_major> af[4];
            wmma::fragment<wmma::matrix_b,16,16,16,__half,wmma::col_major> bf[2];
            #pragma unroll
            for (int mi = 0; mi < 4; mi++)
                wmma::load_matrix_sync(af[mi], &Ab[(wm*64 + mi*16)*72 + k16*16], 72);
            #pragma unroll
            for (int ni = 0; ni < 2; ni++)
                wmma::load_matrix_sync(bf[ni], &Bb[(wn*32 + ni*16)*72 + k16*16], 72);
            #pragma unroll
            for (int mi = 0; mi < 4; mi++)
                #pragma unroll
                for (int ni = 0; ni < 2; ni++)
                    wmma::mma_sync(acc[mi][ni], af[mi], bf[ni], acc[mi][ni]);
        }
        __syncthreads();
    }
    #pragma unroll
    for (int mi = 0; mi < 4; mi++)
        #pragma unroll
        for (int ni = 0; ni < 2; ni++)
            wmma::store_matrix_sync(
                &g_xin[(m0 + wm*64 + mi*16)*(size_t)G_ + n0 + wn*32 + ni*16],
                acc[mi][ni], G_, wmma::mem_row_major);
}

// ============ Stage 2: persistent recurrence (fp16), warp-0 polling, dataflow flags ============
// byte offsets: Ws half 32x1032 @0 (66048B) | Hs half 2x(64x264) @66048 (67584B)
//               Ps float 8x32x36 @133632 (36864B) | Cs 512 @170496 | Bsum 32 @172544
#define RB_WS   0
#define RB_HS   66048
#define RB_PS   133632
#define RB_CS   170496
#define RB_BS   172544
#define SMEM_BYTES 172672
#define HS_BUF  16896                      // halves per Hs buffer (64*264)

__global__ __launch_bounds__(256) void lstm_rec(const float* __restrict__ whh,
                                                const float* __restrict__ bih,
                                                const float* __restrict__ bhh,
                                                float* __restrict__ out,
                                                int layer) {
    extern __shared__ char smc[];
    __half* Ws   = reinterpret_cast<__half*>(smc + RB_WS);
    __half* Hs   = reinterpret_cast<__half*>(smc + RB_HS);
    float*  Ps   = reinterpret_cast<float*>(smc + RB_PS);
    float*  Cs   = reinterpret_cast<float*>(smc + RB_CS);
    float*  Bsum = reinterpret_cast<float*>(smc + RB_BS);

    const int tid  = threadIdx.x;
    const int warp = tid >> 5;
    const int lane = tid & 31;
    const int wm   = warp & 1;            // batch half (32 rows)
    const int wk   = warp >> 1;           // K quarter within each 256-chunk
    const int j0   = blockIdx.x * 8;

    const float* whh_l = whh + (size_t)layer * (size_t)G_ * H_;
    const float* bih_l = bih + (size_t)layer * G_;
    const float* bhh_l = bhh + (size_t)layer * G_;
    float* hn_out = out + TBH + (size_t)layer * BH;
    float* cn_out = out + TBH + 2*(size_t)BH + (size_t)layer * BH;
    const uint32_t hs_b = smem_u32(Hs);

    const int rr_c = tid >> 5;                  // staging row helper
    const int cc8  = (tid & 31) << 3;           // staging col offset (0..248)

    // Stage w_hh rows (n = gate*8 + jj) as fp16.
    #pragma unroll 4
    for (int i = 0; i < 32; i++) {
        int idx = i*256 + tid;
        int rr = idx >> 8;
        int cc = (idx & 255) << 2;
        int grow = (rr >> 3) * H_ + j0 + (rr & 7);
        float4 v = *reinterpret_cast<const float4*>(&whh_l[(size_t)grow * H_ + cc]);
        __half2* d = reinterpret_cast<__half2*>(&Ws[rr*1032 + cc]);
        d[0] = __floats2half2_rn(v.x, v.y);
        d[1] = __floats2half2_rn(v.z, v.w);
    }
    if (tid < 32) {
        int grow = (tid >> 3) * H_ + j0 + (tid & 7);
        Bsum[tid] = bih_l[grow] + bhh_l[grow];
    }
    Cs[tid] = 0.0f; Cs[tid + 256] = 0.0f;
    __syncthreads();

    const int b0 = tid >> 3, jj = tid & 7;
    const int b1 = (tid + 256) >> 3;

    for (int t = 0; t < T_; ++t) {
        const __half* hprev = g_h + (size_t)(t & 1) * BH;
        __half*       hnext = g_h + (size_t)((t + 1) & 1) * BH;
        const unsigned tgt = (unsigned)t;

        // xin prefetch (independent of h) — issued before any waiting
        float xr[8];
        {
            const float* xb = g_xin + (size_t)t * B_ * G_ + j0 + jj;
            const float* p0 = xb + (size_t)b0 * G_;
            const float* p1 = xb + (size_t)b1 * G_;
            xr[0]=p0[0]; xr[1]=p0[1024]; xr[2]=p0[2048]; xr[3]=p0[3072];
            xr[4]=p1[0]; xr[5]=p1[1024]; xr[6]=p1[2048]; xr[7]=p1[3072];
        }

        wmma::fragment<wmma::accumulator,16,16,16,float> acc[2][2];
        #pragma unroll
        for (int mi = 0; mi < 2; mi++)
            #pragma unroll
            for (int ni = 0; ni < 2; ni++)
                wmma::fill_fragment(acc[mi][ni], 0.0f);

        // chunk-0 gate: ONLY warp 0 polls (lane <-> producer CTA), barrier gates the CTA
        if (warp == 0) {
            const unsigned* fl = &g_flag[lane];
            while (ld_acq(fl) < tgt) __nanosleep(64);
        }
        __syncthreads();
        #pragma unroll
        for (int i = 0; i < 8; i++) {
            int rr = rr_c + i*8;
            CP_ASYNC16(hs_b + (uint32_t)(rr*264 + cc8)*2, &hprev[(size_t)rr*H_ + cc8]);
        }
        CP_COMMIT();

        for (int ch = 0; ch < 4; ch++) {
            const int buf = ch & 1;
            if (ch < 3) {
                // gate for next chunk: warp-0 poll, then barrier (also protects buf^1 reuse)
                if (warp == 0) {
                    const unsigned* fl = &g_flag[32*(ch+1) + lane];
                    while (ld_acq(fl) < tgt) __nanosleep(64);
                }
                __syncthreads();
                const int kc = (ch + 1) * 256;
                const uint32_t dh = hs_b + (uint32_t)((buf^1)*HS_BUF)*2;
                #pragma unroll
                for (int i = 0; i < 8; i++) {
                    int rr = rr_c + i*8;
                    CP_ASYNC16(dh + (uint32_t)(rr*264 + cc8)*2, &hprev[(size_t)rr*H_ + kc + cc8]);
                }
                CP_COMMIT();
                CP_WAIT(1);
            } else {
                CP_WAIT(0);
            }
            __syncthreads();                       // Hs[buf] ready
            const __half* Hb = Hs + buf*HS_BUF;
            #pragma unroll
            for (int k16 = 0; k16 < 4; k16++) {
                const int koff = wk*64 + k16*16;
                wmma::fragment<wmma::matrix_a,16,16,16,__half,wmma::row_major> af[2];
                wmma::fragment<wmma::matrix_b,16,16,16,__half,wmma::col_major> bf[2];
                wmma::load_matrix_sync(af[0], &Hb[(wm*32     )*264 + koff], 264);
                wmma::load_matrix_sync(af[1], &Hb[(wm*32 + 16)*264 + koff], 264);
                wmma::load_matrix_sync(bf[0], &Ws[          ch*256 + koff], 1032);
                wmma::load_matrix_sync(bf[1], &Ws[16*1032 + ch*256 + koff], 1032);
                #pragma unroll
                for (int mi = 0; mi < 2; mi++)
                    #pragma unroll
                    for (int ni = 0; ni < 2; ni++)
                        wmma::mma_sync(acc[mi][ni], af[mi], bf[ni], acc[mi][ni]);
            }
        }
        // last-chunk buffer protect + Ps store (per-warp private region)
        __syncthreads();
        #pragma unroll
        for (int mi = 0; mi < 2; mi++)
            #pragma unroll
            for (int ni = 0; ni < 2; ni++)
                wmma::store_matrix_sync(&Ps[warp*1152 + (mi*16)*36 + ni*16],
                                        acc[mi][ni], 36, wmma::mem_row_major);
        __syncthreads();

        // fused K-reduction + gates; store ONLY hnext before publishing
        float hv2[2], cv2[2];
        #pragma unroll
        for (int h2 = 0; h2 < 2; h2++) {
            int e  = tid + h2*256;
            int b  = e >> 3;
            int wmb = b >> 5, br = b & 31;
            float s[4];
            #pragma unroll
            for (int g = 0; g < 4; g++) {
                int n = g*8 + jj;
                float a = Ps[(0*2+wmb)*1152 + br*36 + n]
                        + Ps[(1*2+wmb)*1152 + br*36 + n]
                        + Ps[(2*2+wmb)*1152 + br*36 + n]
                        + Ps[(3*2+wmb)*1152 + br*36 + n];
                s[g] = a + xr[h2*4 + g] + Bsum[n];
            }
            float si = 1.0f / (1.0f + __expf(-s[0]));
            float sf = 1.0f / (1.0f + __expf(-s[1]));
            float so = 1.0f / (1.0f + __expf(-s[3]));
            float cv = sf * Cs[e] + si * tanhf(s[2]);
            float hv = so * tanhf(cv);
            Cs[e] = cv;
            hv2[h2] = hv; cv2[h2] = cv;
            hnext[(size_t)b*H_ + j0 + jj] = __float2half_rn(hv);
        }
        // publish flag ASAP (critical path), then do off-path output stores
        __syncthreads();
        if (tid == 0) {
            __threadfence();
            st_rel(&g_flag[blockIdx.x], (unsigned)(t + 1));
        }
        #pragma unroll
        for (int h2 = 0; h2 < 2; h2++) {
            int b = (tid + h2*256) >> 3;
            if (layer == 0)
                g_s0h[((size_t)t * B_ + b) * H_ + j0 + jj] = __float2half_rn(hv2[h2]);
            else
                out[((size_t)t * B_ + b) * H_ + j0 + jj] = hv2[h2];
            if (t == T_ - 1) {
                hn_out[(size_t)b*H_ + j0 + jj] = hv2[h2];
                cn_out[(size_t)b*H_ + j0 + jj] = cv2[h2];
            }
        }
    }
}

// ---------------- launch ----------------
extern "C" void kernel_launch(void* const* d_in, const int* in_sizes, int n_in,
                              void* d_out, int out_size) {
    const float* x   = (const float*)d_in[0];
    const float* wih = (const float*)d_in[1];
    const float* whh = (const float*)d_in[2];
    const float* bih = (const float*)d_in[3];
    const float* bhh = (const float*)d_in[4];
    float* out = (float*)d_out;

    cudaFuncSetAttribute(lstm_rec, cudaFuncAttributeMaxDynamicSharedMemorySize, SMEM_BYTES);
    cudaFuncSetAttribute(gemm_xin, cudaFuncAttributeMaxDynamicSharedMemorySize, GX_SMEM);

    init_kernel<<<128, 256>>>();                                  // #1
    round_all<<<4096, 256>>>(x, wih);                             // #2
    gemm_xin<<<dim3(32, 256), 256, GX_SMEM>>>(0);                 // #3
    lstm_rec<<<NCTA, 256, SMEM_BYTES>>>(whh, bih, bhh, out, 0);   // #4 -> ncu slot 6
    init_kernel<<<128, 256>>>();
    gemm_xin<<<dim3(32, 256), 256, GX_SMEM>>>(1);
    lstm_rec<<<NCTA, 256, SMEM_BYTES>>>(whh, bih, bhh, out, 1);
}

// round 13
// speedup vs baseline: 1.8474x; 1.1085x over previous
#include <cuda_runtime.h>
#include <cuda_fp16.h>
#include <mma.h>
#include <cstdint>

using namespace nvcuda;

#define T_  512
#define B_  64
#define H_  1024
#define G_  4096
#define BH  (B_*H_)
#define TBH ((size_t)T_*B_*H_)
#define NCTA 128

// ---------------- device scratch (no allocations allowed) ----------------
__device__ float    g_xin[(size_t)T_*B_*G_];     // input projection (fp32, per layer)
__device__ __half   g_xh[TBH];                   // x rounded to fp16
__device__ __half   g_wh[(size_t)2*G_*H_];       // w_ih rounded to fp16
__device__ __half   g_s0h[TBH];                  // layer-0 seq (fp16, feeds layer-1 gemm)
__device__ __half   g_h[2*BH];                   // double-buffered h state (fp16)
__device__ unsigned g_flag[NCTA];                // per-CTA step flags

__device__ __forceinline__ uint32_t smem_u32(const void* p) {
    uint32_t a;
    asm("{ .reg .u64 t; cvta.to.shared.u64 t, %1; cvt.u32.u64 %0, t; }" : "=r"(a) : "l"(p));
    return a;
}
__device__ __forceinline__ unsigned ld_acq(const unsigned* p) {
    unsigned v;
    asm volatile("ld.acquire.gpu.global.u32 %0, [%1];" : "=r"(v) : "l"(p) : "memory");
    return v;
}
__device__ __forceinline__ void st_rel(unsigned* p, unsigned v) {
    asm volatile("st.release.gpu.global.u32 [%0], %1;" :: "l"(p), "r"(v) : "memory");
}
#define CP_ASYNC16(dst_u32, src_ptr) \
    asm volatile("cp.async.cg.shared.global [%0], [%1], 16;" :: "r"(dst_u32), "l"(src_ptr))
#define CP_COMMIT() asm volatile("cp.async.commit_group;" ::: "memory")
#define CP_WAIT(n)  asm volatile("cp.async.wait_group %0;" :: "n"(n) : "memory")
#define BAR_SYNC(id, cnt)   asm volatile("bar.sync %0, %1;"   :: "r"(id), "r"(cnt) : "memory")
#define BAR_ARRIVE(id, cnt) asm volatile("bar.arrive %0, %1;" :: "r"(id), "r"(cnt) : "memory")

// ---------------- init: zero h buffers + flags ----------------
__global__ void init_kernel() {
    int i = blockIdx.x * blockDim.x + threadIdx.x;   // 32768 threads
    float* hz = reinterpret_cast<float*>(g_h);
    hz[i] = 0.0f; hz[i + 32768] = 0.0f;
    if (i < NCTA) g_flag[i] = 0u;
}

// ---------------- pre-round x and w_ih to fp16 ----------------
#define XF4 (TBH/4)
#define WF4 ((size_t)2*G_*H_/4)
__global__ void round_all(const float* __restrict__ x, const float* __restrict__ wih) {
    const size_t stride = (size_t)gridDim.x * blockDim.x;
    for (size_t i = (size_t)blockIdx.x * blockDim.x + threadIdx.x; i < XF4 + WF4; i += stride) {
        float4 v; __half2* dst;
        if (i < XF4) {
            v = reinterpret_cast<const float4*>(x)[i];
            dst = reinterpret_cast<__half2*>(g_xh) + i * 2;
        } else {
            v = reinterpret_cast<const float4*>(wih)[i - XF4];
            dst = reinterpret_cast<__half2*>(g_wh) + (i - XF4) * 2;
        }
        dst[0] = __floats2half2_rn(v.x, v.y);
        dst[1] = __floats2half2_rn(v.z, v.w);
    }
}

// ============ Stage 1: xin[32768,4096] = A[32768,1024] @ W[4096,1024]^T (fp16) ============
#define GA 9216
#define GX_SMEM (4*GA*2)
__global__ __launch_bounds__(256) void gemm_xin(int layer) {
    extern __shared__ __half smh[];
    __half* As = smh;
    __half* Bs = smh + 2*GA;

    const __half* A = (layer == 0) ? g_xh : g_s0h;
    const __half* W = g_wh + (size_t)layer * (size_t)G_ * H_;

    const int tid  = threadIdx.x;
    const int warp = tid >> 5;
    const int wm   = warp >> 2;
    const int wn   = warp & 3;
    const size_t m0 = (size_t)blockIdx.y * 128;
    const int    n0 = blockIdx.x * 128;

    const int r8 = tid >> 3, c8 = (tid & 7) << 3;
    const uint32_t sa = smem_u32(As), sb = smem_u32(Bs);

    wmma::fragment<wmma::accumulator,16,16,16,float> acc[4][2];
    #pragma unroll
    for (int mi = 0; mi < 4; mi++)
        #pragma unroll
        for (int ni = 0; ni < 2; ni++)
            wmma::fill_fragment(acc[mi][ni], 0.0f);

    #pragma unroll
    for (int i = 0; i < 4; i++) {
        int rr = r8 + i*32;
        CP_ASYNC16(sa + (uint32_t)(rr*72 + c8)*2, &A[(m0 + rr)*1024 + c8]);
        CP_ASYNC16(sb + (uint32_t)(rr*72 + c8)*2, &W[(size_t)(n0 + rr)*1024 + c8]);
    }
    CP_COMMIT();

    for (int it = 0; it < 16; ++it) {
        const int buf = it & 1;
        if (it < 15) {
            const int kc = (it + 1) * 64;
            const uint32_t da = sa + (uint32_t)((buf^1)*GA)*2;
            const uint32_t db = sb + (uint32_t)((buf^1)*GA)*2;
            #pragma unroll
            for (int i = 0; i < 4; i++) {
                int rr = r8 + i*32;
                CP_ASYNC16(da + (uint32_t)(rr*72 + c8)*2, &A[(m0 + rr)*1024 + kc + c8]);
                CP_ASYNC16(db + (uint32_t)(rr*72 + c8)*2, &W[(size_t)(n0 + rr)*1024 + kc + c8]);
            }
            CP_COMMIT();
            CP_WAIT(1);
        } else {
            CP_WAIT(0);
        }
        __syncthreads();
        const __half* Ab = As + buf*GA;
        const __half* Bb = Bs + buf*GA;
        #pragma unroll
        for (int k16 = 0; k16 < 4; k16++) {
            wmma::fragment<wmma::matrix_a,16,16,16,__half,wmma::row_major> af[4];
            wmma::fragment<wmma::matrix_b,16,16,16,__half,wmma::col_major> bf[2];
            #pragma unroll
            for (int mi = 0; mi < 4; mi++)
                wmma::load_matrix_sync(af[mi], &Ab[(wm*64 + mi*16)*72 + k16*16], 72);
            #pragma unroll
            for (int ni = 0; ni < 2; ni++)
                wmma::load_matrix_sync(bf[ni], &Bb[(wn*32 + ni*16)*72 + k16*16], 72);
            #pragma unroll
            for (int mi = 0; mi < 4; mi++)
                #pragma unroll
                for (int ni = 0; ni < 2; ni++)
                    wmma::mma_sync(acc[mi][ni], af[mi], bf[ni], acc[mi][ni]);
        }
        __syncthreads();
    }
    #pragma unroll
    for (int mi = 0; mi < 4; mi++)
        #pragma unroll
        for (int ni = 0; ni < 2; ni++)
            wmma::store_matrix_sync(
                &g_xin[(m0 + wm*64 + mi*16)*(size_t)G_ + n0 + wn*32 + ni*16],
                acc[mi][ni], G_, wmma::mem_row_major);
}

// ============ Stage 2: persistent recurrence, warp-specialized loader ============
// 288 threads: warps 0-7 mma/epilogue, warp 8 loader (polls flags + cp.async).
// byte offsets: Ws half 32x1032 @0 (66048B) | Hs half 2x(64x264) @66048 (67584B)
//               Ps float 8x32x36 @133632 (36864B) | Cs 512 @170496 | Bsum 32 @172544
#define RB_WS   0
#define RB_HS   66048
#define RB_PS   133632
#define RB_CS   170496
#define RB_BS   172544
#define SMEM_BYTES 172672
#define HS_BUF  16896                      // halves per Hs buffer (64*264)
// named barriers: READY[p]=1+p (loader->mma), FREE[p]=3+p (mma->loader), EPI=5 (mma only)
#define BR_READY(p) (1 + (p))
#define BR_FREE(p)  (3 + (p))
#define BR_EPI      5

__global__ __launch_bounds__(288) void lstm_rec(const float* __restrict__ whh,
                                                const float* __restrict__ bih,
                                                const float* __restrict__ bhh,
                                                float* __restrict__ out,
                                                int layer) {
    extern __shared__ char smc[];
    __half* Ws   = reinterpret_cast<__half*>(smc + RB_WS);
    __half* Hs   = reinterpret_cast<__half*>(smc + RB_HS);
    float*  Ps   = reinterpret_cast<float*>(smc + RB_PS);
    float*  Cs   = reinterpret_cast<float*>(smc + RB_CS);
    float*  Bsum = reinterpret_cast<float*>(smc + RB_BS);

    const int tid  = threadIdx.x;
    const int warp = tid >> 5;
    const int lane = tid & 31;
    const int j0   = blockIdx.x * 8;

    const float* whh_l = whh + (size_t)layer * (size_t)G_ * H_;
    const float* bih_l = bih + (size_t)layer * G_;
    const float* bhh_l = bhh + (size_t)layer * G_;
    float* hn_out = out + TBH + (size_t)layer * BH;
    float* cn_out = out + TBH + 2*(size_t)BH + (size_t)layer * BH;
    const uint32_t hs_b = smem_u32(Hs);

    // ---- prologue: stage w_hh (fp16), bias, c=0 (mma threads only) ----
    if (tid < 256) {
        #pragma unroll 4
        for (int i = 0; i < 32; i++) {
            int idx = i*256 + tid;
            int rr = idx >> 8;
            int cc = (idx & 255) << 2;
            int grow = (rr >> 3) * H_ + j0 + (rr & 7);
            float4 v = *reinterpret_cast<const float4*>(&whh_l[(size_t)grow * H_ + cc]);
            __half2* d = reinterpret_cast<__half2*>(&Ws[rr*1032 + cc]);
            d[0] = __floats2half2_rn(v.x, v.y);
            d[1] = __floats2half2_rn(v.z, v.w);
        }
        if (tid < 32) {
            int grow = (tid >> 3) * H_ + j0 + (tid & 7);
            Bsum[tid] = bih_l[grow] + bhh_l[grow];
        }
        Cs[tid] = 0.0f; Cs[tid + 256] = 0.0f;
    }
    __syncthreads();   // all 288

    if (warp == 8) {
        // ================= LOADER WARP =================
        for (int t = 0; t < T_; ++t) {
            const __half* hprev = g_h + (size_t)(t & 1) * BH;
            const unsigned tgt = (unsigned)t;
            #pragma unroll
            for (int ch = 0; ch < 4; ch++) {
                const int p = ch & 1;
                if (t > 0 || ch >= 2) BAR_SYNC(BR_FREE(p), 288);
                // poll the 32 producers of this chunk (one flag per lane)
                {
                    const unsigned* fl = &g_flag[32*ch + lane];
                    while (ld_acq(fl) < tgt) __nanosleep(40);
                }
                // fill Hs[p]: 64 rows x 256 cols; lane owns one 8-col unit
                const int kc = ch * 256;
                const uint32_t dst0 = hs_b + (uint32_t)(p*HS_BUF + lane*8)*2;
                const __half* src0 = hprev + kc + lane*8;
                #pragma unroll 8
                for (int rr = 0; rr < 64; rr++)
                    CP_ASYNC16(dst0 + (uint32_t)(rr*264)*2, src0 + (size_t)rr*H_);
                CP_COMMIT();
                if (ch >= 1) { CP_WAIT(1); BAR_ARRIVE(BR_READY((ch-1)&1), 288); }
            }
            CP_WAIT(0);
            BAR_ARRIVE(BR_READY(1), 288);
        }
    } else {
        // ================= MMA / EPILOGUE WARPS =================
        const int wm = warp & 1;            // batch half (32 rows)
        const int wk = warp >> 1;           // K quarter within each 256-chunk
        const int b0 = tid >> 3, jj = tid & 7;
        const int b1 = (tid + 256) >> 3;

        for (int t = 0; t < T_; ++t) {
            __half* hnext = g_h + (size_t)((t + 1) & 1) * BH;

            // xin prefetch (independent of h)
            float xr[8];
            {
                const float* xb = g_xin + (size_t)t * B_ * G_ + j0 + jj;
                const float* p0 = xb + (size_t)b0 * G_;
                const float* p1 = xb + (size_t)b1 * G_;
                xr[0]=p0[0]; xr[1]=p0[1024]; xr[2]=p0[2048]; xr[3]=p0[3072];
                xr[4]=p1[0]; xr[5]=p1[1024]; xr[6]=p1[2048]; xr[7]=p1[3072];
            }

            wmma::fragment<wmma::accumulator,16,16,16,float> acc[2][2];
            #pragma unroll
            for (int mi = 0; mi < 2; mi++)
                #pragma unroll
                for (int ni = 0; ni < 2; ni++)
                    wmma::fill_fragment(acc[mi][ni], 0.0f);

            #pragma unroll
            for (int ch = 0; ch < 4; ch++) {
                const int p = ch & 1;
                BAR_SYNC(BR_READY(p), 288);            // buffer p filled for chunk ch
                const __half* Hb = Hs + p*HS_BUF;
                #pragma unroll
                for (int k16 = 0; k16 < 4; k16++) {
                    const int koff = wk*64 + k16*16;
                    wmma::fragment<wmma::matrix_a,16,16,16,__half,wmma::row_major> af[2];
                    wmma::fragment<wmma::matrix_b,16,16,16,__half,wmma::col_major> bf[2];
                    wmma::load_matrix_sync(af[0], &Hb[(wm*32     )*264 + koff], 264);
                    wmma::load_matrix_sync(af[1], &Hb[(wm*32 + 16)*264 + koff], 264);
                    wmma::load_matrix_sync(bf[0], &Ws[          ch*256 + koff], 1032);
                    wmma::load_matrix_sync(bf[1], &Ws[16*1032 + ch*256 + koff], 1032);
                    #pragma unroll
                    for (int mi = 0; mi < 2; mi++)
                        #pragma unroll
                        for (int ni = 0; ni < 2; ni++)
                            wmma::mma_sync(acc[mi][ni], af[mi], bf[ni], acc[mi][ni]);
                }
                BAR_ARRIVE(BR_FREE(p), 288);           // buffer p consumed
            }

            // per-warp partials -> Ps
            #pragma unroll
            for (int mi = 0; mi < 2; mi++)
                #pragma unroll
                for (int ni = 0; ni < 2; ni++)
                    wmma::store_matrix_sync(&Ps[warp*1152 + (mi*16)*36 + ni*16],
                                            acc[mi][ni], 36, wmma::mem_row_major);
            BAR_SYNC(BR_EPI, 256);

            // fused K-reduction + gates; store ONLY hnext before publishing
            float hv2[2], cv2[2];
            #pragma unroll
            for (int h2 = 0; h2 < 2; h2++) {
                int e  = tid + h2*256;
                int b  = e >> 3;
                int wmb = b >> 5, br = b & 31;
                float s[4];
                #pragma unroll
                for (int g = 0; g < 4; g++) {
                    int n = g*8 + jj;
                    float a = Ps[(0*2+wmb)*1152 + br*36 + n]
                            + Ps[(1*2+wmb)*1152 + br*36 + n]
                            + Ps[(2*2+wmb)*1152 + br*36 + n]
                            + Ps[(3*2+wmb)*1152 + br*36 + n];
                    s[g] = a + xr[h2*4 + g] + Bsum[n];
                }
                float si = 1.0f / (1.0f + __expf(-s[0]));
                float sf = 1.0f / (1.0f + __expf(-s[1]));
                float so = 1.0f / (1.0f + __expf(-s[3]));
                float cv = sf * Cs[e] + si * tanhf(s[2]);
                float hv = so * tanhf(cv);
                Cs[e] = cv;
                hv2[h2] = hv; cv2[h2] = cv;
                hnext[(size_t)b*H_ + j0 + jj] = __float2half_rn(hv);
            }
            BAR_SYNC(BR_EPI, 256);
            if (tid == 0) {
                __threadfence();
                st_rel(&g_flag[blockIdx.x], (unsigned)(t + 1));
            }
            // off-critical-path output stores
            #pragma unroll
            for (int h2 = 0; h2 < 2; h2++) {
                int b = (tid + h2*256) >> 3;
                if (layer == 0)
                    g_s0h[((size_t)t * B_ + b) * H_ + j0 + jj] = __float2half_rn(hv2[h2]);
                else
                    out[((size_t)t * B_ + b) * H_ + j0 + jj] = hv2[h2];
                if (t == T_ - 1) {
                    hn_out[(size_t)b*H_ + j0 + jj] = hv2[h2];
                    cn_out[(size_t)b*H_ + j0 + jj] = cv2[h2];
                }
            }
        }
    }
}

// ---------------- launch ----------------
extern "C" void kernel_launch(void* const* d_in, const int* in_sizes, int n_in,
                              void* d_out, int out_size) {
    const float* x   = (const float*)d_in[0];
    const float* wih = (const float*)d_in[1];
    const float* whh = (const float*)d_in[2];
    const float* bih = (const float*)d_in[3];
    const float* bhh = (const float*)d_in[4];
    float* out = (float*)d_out;

    cudaFuncSetAttribute(lstm_rec, cudaFuncAttributeMaxDynamicSharedMemorySize, SMEM_BYTES);
    cudaFuncSetAttribute(gemm_xin, cudaFuncAttributeMaxDynamicSharedMemorySize, GX_SMEM);

    init_kernel<<<128, 256>>>();                                  // #1
    round_all<<<4096, 256>>>(x, wih);                             // #2
    gemm_xin<<<dim3(32, 256), 256, GX_SMEM>>>(0);                 // #3
    lstm_rec<<<NCTA, 288, SMEM_BYTES>>>(whh, bih, bhh, out, 0);   // #4 -> ncu slot 6
    init_kernel<<<128, 256>>>();
    gemm_xin<<<dim3(32, 256), 256, GX_SMEM>>>(1);
    lstm_rec<<<NCTA, 288, SMEM_BYTES>>>(whh, bih, bhh, out, 1);
}

// round 14
// speedup vs baseline: 1.8929x; 1.0247x over previous
#include <cuda_runtime.h>
#include <cuda_fp16.h>
#include <mma.h>
#include <cstdint>

using namespace nvcuda;

#define T_  512
#define B_  64
#define H_  1024
#define G_  4096
#define BH  (B_*H_)
#define TBH ((size_t)T_*B_*H_)
#define NCTA 128

// ---------------- device scratch (no allocations allowed) ----------------
__device__ float    g_xin[(size_t)T_*B_*G_];     // input projection (fp32, per layer)
__device__ __half   g_xh[TBH];                   // x rounded to fp16
__device__ __half   g_wh[(size_t)2*G_*H_];       // w_ih rounded to fp16
__device__ __half   g_s0h[TBH];                  // layer-0 seq (fp16, feeds layer-1 gemm)
__device__ __half   g_h[2*BH];                   // double-buffered h state (fp16)
__device__ unsigned g_flag[NCTA];                // per-CTA step flags

__device__ __forceinline__ uint32_t smem_u32(const void* p) {
    uint32_t a;
    asm("{ .reg .u64 t; cvta.to.shared.u64 t, %1; cvt.u32.u64 %0, t; }" : "=r"(a) : "l"(p));
    return a;
}
__device__ __forceinline__ unsigned ld_acq(const unsigned* p) {
    unsigned v;
    asm volatile("ld.acquire.gpu.global.u32 %0, [%1];" : "=r"(v) : "l"(p) : "memory");
    return v;
}
__device__ __forceinline__ void st_rel(unsigned* p, unsigned v) {
    asm volatile("st.release.gpu.global.u32 [%0], %1;" :: "l"(p), "r"(v) : "memory");
}
#define CP_ASYNC16(dst_u32, src_ptr) \
    asm volatile("cp.async.cg.shared.global [%0], [%1], 16;" :: "r"(dst_u32), "l"(src_ptr))
#define CP_COMMIT() asm volatile("cp.async.commit_group;" ::: "memory")
#define CP_WAIT(n)  asm volatile("cp.async.wait_group %0;" :: "n"(n) : "memory")
#define BAR_SYNC(id, cnt)   asm volatile("bar.sync %0, %1;"   :: "r"(id), "r"(cnt) : "memory")
#define BAR_ARRIVE(id, cnt) asm volatile("bar.arrive %0, %1;" :: "r"(id), "r"(cnt) : "memory")

// ---------------- init: zero h buffers + flags ----------------
__global__ void init_kernel() {
    int i = blockIdx.x * blockDim.x + threadIdx.x;   // 32768 threads
    float* hz = reinterpret_cast<float*>(g_h);
    hz[i] = 0.0f; hz[i + 32768] = 0.0f;
    if (i < NCTA) g_flag[i] = 0u;
}

// ---------------- pre-round x and w_ih to fp16 ----------------
#define XF4 (TBH/4)
#define WF4 ((size_t)2*G_*H_/4)
__global__ void round_all(const float* __restrict__ x, const float* __restrict__ wih) {
    const size_t stride = (size_t)gridDim.x * blockDim.x;
    for (size_t i = (size_t)blockIdx.x * blockDim.x + threadIdx.x; i < XF4 + WF4; i += stride) {
        float4 v; __half2* dst;
        if (i < XF4) {
            v = reinterpret_cast<const float4*>(x)[i];
            dst = reinterpret_cast<__half2*>(g_xh) + i * 2;
        } else {
            v = reinterpret_cast<const float4*>(wih)[i - XF4];
            dst = reinterpret_cast<__half2*>(g_wh) + (i - XF4) * 2;
        }
        dst[0] = __floats2half2_rn(v.x, v.y);
        dst[1] = __floats2half2_rn(v.z, v.w);
    }
}

// ============ Stage 1: xin[32768,4096] = A[32768,1024] @ W[4096,1024]^T (fp16) ============
#define GA 9216
#define GX_SMEM (4*GA*2)
__global__ __launch_bounds__(256) void gemm_xin(int layer) {
    extern __shared__ __half smh[];
    __half* As = smh;
    __half* Bs = smh + 2*GA;

    const __half* A = (layer == 0) ? g_xh : g_s0h;
    const __half* W = g_wh + (size_t)layer * (size_t)G_ * H_;

    const int tid  = threadIdx.x;
    const int warp = tid >> 5;
    const int wm   = warp >> 2;
    const int wn   = warp & 3;
    const size_t m0 = (size_t)blockIdx.y * 128;
    const int    n0 = blockIdx.x * 128;

    const int r8 = tid >> 3, c8 = (tid & 7) << 3;
    const uint32_t sa = smem_u32(As), sb = smem_u32(Bs);

    wmma::fragment<wmma::accumulator,16,16,16,float> acc[4][2];
    #pragma unroll
    for (int mi = 0; mi < 4; mi++)
        #pragma unroll
        for (int ni = 0; ni < 2; ni++)
            wmma::fill_fragment(acc[mi][ni], 0.0f);

    #pragma unroll
    for (int i = 0; i < 4; i++) {
        int rr = r8 + i*32;
        CP_ASYNC16(sa + (uint32_t)(rr*72 + c8)*2, &A[(m0 + rr)*1024 + c8]);
        CP_ASYNC16(sb + (uint32_t)(rr*72 + c8)*2, &W[(size_t)(n0 + rr)*1024 + c8]);
    }
    CP_COMMIT();

    for (int it = 0; it < 16; ++it) {
        const int buf = it & 1;
        if (it < 15) {
            const int kc = (it + 1) * 64;
            const uint32_t da = sa + (uint32_t)((buf^1)*GA)*2;
            const uint32_t db = sb + (uint32_t)((buf^1)*GA)*2;
            #pragma unroll
            for (int i = 0; i < 4; i++) {
                int rr = r8 + i*32;
                CP_ASYNC16(da + (uint32_t)(rr*72 + c8)*2, &A[(m0 + rr)*1024 + kc + c8]);
                CP_ASYNC16(db + (uint32_t)(rr*72 + c8)*2, &W[(size_t)(n0 + rr)*1024 + kc + c8]);
            }
            CP_COMMIT();
            CP_WAIT(1);
        } else {
            CP_WAIT(0);
        }
        __syncthreads();
        const __half* Ab = As + buf*GA;
        const __half* Bb = Bs + buf*GA;
        #pragma unroll
        for (int k16 = 0; k16 < 4; k16++) {
            wmma::fragment<wmma::matrix_a,16,16,16,__half,wmma::row_major> af[4];
            wmma::fragment<wmma::matrix_b,16,16,16,__half,wmma::col_major> bf[2];
            #pragma unroll
            for (int mi = 0; mi < 4; mi++)
                wmma::load_matrix_sync(af[mi], &Ab[(wm*64 + mi*16)*72 + k16*16], 72);
            #pragma unroll
            for (int ni = 0; ni < 2; ni++)
                wmma::load_matrix_sync(bf[ni], &Bb[(wn*32 + ni*16)*72 + k16*16], 72);
            #pragma unroll
            for (int mi = 0; mi < 4; mi++)
                #pragma unroll
                for (int ni = 0; ni < 2; ni++)
                    wmma::mma_sync(acc[mi][ni], af[mi], bf[ni], acc[mi][ni]);
        }
        __syncthreads();
    }
    #pragma unroll
    for (int mi = 0; mi < 4; mi++)
        #pragma unroll
        for (int ni = 0; ni < 2; ni++)
            wmma::store_matrix_sync(
                &g_xin[(m0 + wm*64 + mi*16)*(size_t)G_ + n0 + wn*32 + ni*16],
                acc[mi][ni], G_, wmma::mem_row_major);
}

// ============ Stage 2: persistent recurrence, 2 loader warps, 3-buffer rotation ============
// 320 threads: warps 0-7 mma/epilogue, warps 8-9 loaders.
// byte offsets: Ws half 32x1032 @0 (66048B) | Hs half 3x(64x264) @66048 (101376B)
//               Ps float 8x32x36 @167424 (36864B) | Cs 512 @204288 | Bsum 32 @206336
#define RB_WS   0
#define RB_HS   66048
#define RB_PS   167424
#define RB_CS   204288
#define RB_BS   206336
#define SMEM_BYTES 206464
#define HS_BUF  16896                      // halves per Hs buffer (64*264)
#define NBUF    3
// named barriers: READY[p]=1+p (loaders->mma), FREE[p]=4+p (mma->loaders), EPI=7 (mma only)
#define BR_READY(p) (1 + (p))
#define BR_FREE(p)  (4 + (p))
#define BR_EPI      7

__global__ __launch_bounds__(320) void lstm_rec(const float* __restrict__ whh,
                                                const float* __restrict__ bih,
                                                const float* __restrict__ bhh,
                                                float* __restrict__ out,
                                                int layer) {
    extern __shared__ char smc[];
    __half* Ws   = reinterpret_cast<__half*>(smc + RB_WS);
    __half* Hs   = reinterpret_cast<__half*>(smc + RB_HS);
    float*  Ps   = reinterpret_cast<float*>(smc + RB_PS);
    float*  Cs   = reinterpret_cast<float*>(smc + RB_CS);
    float*  Bsum = reinterpret_cast<float*>(smc + RB_BS);

    const int tid  = threadIdx.x;
    const int warp = tid >> 5;
    const int lane = tid & 31;
    const int j0   = blockIdx.x * 8;

    const float* whh_l = whh + (size_t)layer * (size_t)G_ * H_;
    const float* bih_l = bih + (size_t)layer * G_;
    const float* bhh_l = bhh + (size_t)layer * G_;
    float* hn_out = out + TBH + (size_t)layer * BH;
    float* cn_out = out + TBH + 2*(size_t)BH + (size_t)layer * BH;
    const uint32_t hs_b = smem_u32(Hs);

    // ---- prologue: stage w_hh (fp16), bias, c=0 (mma threads only) ----
    if (tid < 256) {
        #pragma unroll 4
        for (int i = 0; i < 32; i++) {
            int idx = i*256 + tid;
            int rr = idx >> 8;
            int cc = (idx & 255) << 2;
            int grow = (rr >> 3) * H_ + j0 + (rr & 7);
            float4 v = *reinterpret_cast<const float4*>(&whh_l[(size_t)grow * H_ + cc]);
            __half2* d = reinterpret_cast<__half2*>(&Ws[rr*1032 + cc]);
            d[0] = __floats2half2_rn(v.x, v.y);
            d[1] = __floats2half2_rn(v.z, v.w);
        }
        if (tid < 32) {
            int grow = (tid >> 3) * H_ + j0 + (tid & 7);
            Bsum[tid] = bih_l[grow] + bhh_l[grow];
        }
        Cs[tid] = 0.0f; Cs[tid + 256] = 0.0f;
    }
    __syncthreads();   // all 320

    if (warp >= 8) {
        // ================= LOADER WARPS (8: rows 0-31, 9: rows 32-63) =================
        const int lrow0 = (warp - 8) * 32;
        int pc = 0;                                  // global chunk counter
        for (int t = 0; t < T_; ++t) {
            const __half* hprev = g_h + (size_t)(t & 1) * BH;
            const unsigned tgt = (unsigned)t;
            int pprev = 0;
            #pragma unroll
            for (int ch = 0; ch < 4; ch++) {
                const int p = pc % NBUF;
                if (pc >= NBUF) BAR_SYNC(BR_FREE(p), 320);
                // poll the 32 producers of this chunk (one flag per lane)
                {
                    const unsigned* fl = &g_flag[32*ch + lane];
                    while (ld_acq(fl) < tgt) __nanosleep(40);
                }
                // fill this warp's 32 rows of Hs[p]
                const int kc = ch * 256;
                const uint32_t dst0 = hs_b + (uint32_t)(p*HS_BUF + lrow0*264 + lane*8)*2;
                const __half* src0 = hprev + (size_t)lrow0*H_ + kc + lane*8;
                #pragma unroll 8
                for (int rr = 0; rr < 32; rr++)
                    CP_ASYNC16(dst0 + (uint32_t)(rr*264)*2, src0 + (size_t)rr*H_);
                CP_COMMIT();
                if (ch >= 1) { CP_WAIT(1); BAR_ARRIVE(BR_READY(pprev), 320); }
                pprev = p; pc++;
            }
            // arm last chunk of this step BEFORE touching t+1 flags (deadlock-safe)
            CP_WAIT(0);
            BAR_ARRIVE(BR_READY(pprev), 320);
        }
    } else {
        // ================= MMA / EPILOGUE WARPS =================
        const int wm = warp & 1;            // batch half (32 rows)
        const int wk = warp >> 1;           // K quarter within each 256-chunk
        const int b0 = tid >> 3, jj = tid & 7;
        const int b1 = (tid + 256) >> 3;
        int pc = 0;

        for (int t = 0; t < T_; ++t) {
            __half* hnext = g_h + (size_t)((t + 1) & 1) * BH;

            // xin prefetch (independent of h)
            float xr[8];
            {
                const float* xb = g_xin + (size_t)t * B_ * G_ + j0 + jj;
                const float* p0 = xb + (size_t)b0 * G_;
                const float* p1 = xb + (size_t)b1 * G_;
                xr[0]=p0[0]; xr[1]=p0[1024]; xr[2]=p0[2048]; xr[3]=p0[3072];
                xr[4]=p1[0]; xr[5]=p1[1024]; xr[6]=p1[2048]; xr[7]=p1[3072];
            }

            wmma::fragment<wmma::accumulator,16,16,16,float> acc[2][2];
            #pragma unroll
            for (int mi = 0; mi < 2; mi++)
                #pragma unroll
                for (int ni = 0; ni < 2; ni++)
                    wmma::fill_fragment(acc[mi][ni], 0.0f);

            #pragma unroll
            for (int ch = 0; ch < 4; ch++) {
                const int p = pc % NBUF; pc++;
                BAR_SYNC(BR_READY(p), 320);            // buffer p filled for chunk ch
                const __half* Hb = Hs + p*HS_BUF;
                #pragma unroll
                for (int k16 = 0; k16 < 4; k16++) {
                    const int koff = wk*64 + k16*16;
                    wmma::fragment<wmma::matrix_a,16,16,16,__half,wmma::row_major> af[2];
                    wmma::fragment<wmma::matrix_b,16,16,16,__half,wmma::col_major> bf[2];
                    wmma::load_matrix_sync(af[0], &Hb[(wm*32     )*264 + koff], 264);
                    wmma::load_matrix_sync(af[1], &Hb[(wm*32 + 16)*264 + koff], 264);
                    wmma::load_matrix_sync(bf[0], &Ws[          ch*256 + koff], 1032);
                    wmma::load_matrix_sync(bf[1], &Ws[16*1032 + ch*256 + koff], 1032);
                    #pragma unroll
                    for (int mi = 0; mi < 2; mi++)
                        #pragma unroll
                        for (int ni = 0; ni < 2; ni++)
                            wmma::mma_sync(acc[mi][ni], af[mi], bf[ni], acc[mi][ni]);
                }
                BAR_ARRIVE(BR_FREE(p), 320);           // buffer p consumed
            }

            // per-warp partials -> Ps
            #pragma unroll
            for (int mi = 0; mi < 2; mi++)
                #pragma unroll
                for (int ni = 0; ni < 2; ni++)
                    wmma::store_matrix_sync(&Ps[warp*1152 + (mi*16)*36 + ni*16],
                                            acc[mi][ni], 36, wmma::mem_row_major);
            BAR_SYNC(BR_EPI, 256);

            // fused K-reduction + gates; store ONLY hnext before publishing
            float hv2[2], cv2[2];
            #pragma unroll
            for (int h2 = 0; h2 < 2; h2++) {
                int e  = tid + h2*256;
                int b  = e >> 3;
                int wmb = b >> 5, br = b & 31;
                float s[4];
                #pragma unroll
                for (int g = 0; g < 4; g++) {
                    int n = g*8 + jj;
                    float a = Ps[(0*2+wmb)*1152 + br*36 + n]
                            + Ps[(1*2+wmb)*1152 + br*36 + n]
                            + Ps[(2*2+wmb)*1152 + br*36 + n]
                            + Ps[(3*2+wmb)*1152 + br*36 + n];
                    s[g] = a + xr[h2*4 + g] + Bsum[n];
                }
                float si = 1.0f / (1.0f + __expf(-s[0]));
                float sf = 1.0f / (1.0f + __expf(-s[1]));
                float so = 1.0f / (1.0f + __expf(-s[3]));
                float cv = sf * Cs[e] + si * tanhf(s[2]);
                float hv = so * tanhf(cv);
                Cs[e] = cv;
                hv2[h2] = hv; cv2[h2] = cv;
                hnext[(size_t)b*H_ + j0 + jj] = __float2half_rn(hv);
            }
            BAR_SYNC(BR_EPI, 256);
            if (tid == 0) {
                __threadfence();
                st_rel(&g_flag[blockIdx.x], (unsigned)(t + 1));
            }
            // off-critical-path output stores
            #pragma unroll
            for (int h2 = 0; h2 < 2; h2++) {
                int b = (tid + h2*256) >> 3;
                if (layer == 0)
                    g_s0h[((size_t)t * B_ + b) * H_ + j0 + jj] = __float2half_rn(hv2[h2]);
                else
                    out[((size_t)t * B_ + b) * H_ + j0 + jj] = hv2[h2];
                if (t == T_ - 1) {
                    hn_out[(size_t)b*H_ + j0 + jj] = hv2[h2];
                    cn_out[(size_t)b*H_ + j0 + jj] = cv2[h2];
                }
            }
        }
    }
}

// ---------------- launch ----------------
extern "C" void kernel_launch(void* const* d_in, const int* in_sizes, int n_in,
                              void* d_out, int out_size) {
    const float* x   = (const float*)d_in[0];
    const float* wih = (const float*)d_in[1];
    const float* whh = (const float*)d_in[2];
    const float* bih = (const float*)d_in[3];
    const float* bhh = (const float*)d_in[4];
    float* out = (float*)d_out;

    cudaFuncSetAttribute(lstm_rec, cudaFuncAttributeMaxDynamicSharedMemorySize, SMEM_BYTES);
    cudaFuncSetAttribute(gemm_xin, cudaFuncAttributeMaxDynamicSharedMemorySize, GX_SMEM);

    init_kernel<<<128, 256>>>();                                  // #1
    round_all<<<4096, 256>>>(x, wih);                             // #2
    gemm_xin<<<dim3(32, 256), 256, GX_SMEM>>>(0);                 // #3
    lstm_rec<<<NCTA, 320, SMEM_BYTES>>>(whh, bih, bhh, out, 0);   // #4 -> ncu slot 6
    init_kernel<<<128, 256>>>();
    gemm_xin<<<dim3(32, 256), 256, GX_SMEM>>>(1);
    lstm_rec<<<NCTA, 320, SMEM_BYTES>>>(whh, bih, bhh, out, 1);
}